// round 15
// baseline (speedup 1.0000x reference)
#include <cuda_runtime.h>
#include <cuda_bf16.h>
#include <cuda_fp16.h>
#include <cstdint>

// ConvMultiStepAttention, B=16, C=T=S=1024.
//   targetT[b,t,d] = (base[b,d,t] + sum_c W[d,c] x[b,c,t] + bias[d]) * sqrt(0.5)
//   scores[b,t,s]  = sum_c targetT[b,t,c] * topT[b,s,c]
//   attn = softmax_S(scores)   (in d_out, in-place, fused fp16 write)
//   ctx[b,c,t]     = sum_s comb[b,c,s] * attn[b,t,s]
// GEMM1/2: split-bf16 (hh+hl+lh, fp32 acc). GEMM3: single fp16 pass.
// R15: R14 kernels unchanged; GEMM2/softmax/GEMM3 split into 2 half-batch
//      segments so the DRAM-bound softmax overlaps the MMA-bound GEMM tails.

#define SCALE_W 0.70710678118654752440f

constexpr int Bb = 16;
constexpr size_t MB1 = 1024 * 1024;
constexpr int HB = Bb / 2;             // half-batch

// ---------------- scratch ----------------------------------------------------
__device__ __nv_bfloat16 g_W_h[MB1],         g_W_l[MB1];
__device__ __nv_bfloat16 g_xT_h[Bb * MB1],   g_xT_l[Bb * MB1];
__device__ __nv_bfloat16 g_topT_h[Bb * MB1], g_topT_l[Bb * MB1];
__device__ __nv_bfloat16 g_tgt_h[Bb * MB1],  g_tgt_l[Bb * MB1];
__device__ __half        g_comb_f[Bb * MB1];
__device__ __half        g_attn_f[Bb * MB1];

// ---------------- host-side stream/event handles (created pre-checkpoint) ------
struct SideStream {
    cudaStream_t s2;
    cudaEvent_t  fork, join;
    cudaEvent_t  e_g2[2], e_sm[2];
    SideStream() {
        cudaStreamCreateWithFlags(&s2, cudaStreamNonBlocking);
        cudaEventCreateWithFlags(&fork, cudaEventDisableTiming);
        cudaEventCreateWithFlags(&join, cudaEventDisableTiming);
        for (int i = 0; i < 2; i++) {
            cudaEventCreateWithFlags(&e_g2[i], cudaEventDisableTiming);
            cudaEventCreateWithFlags(&e_sm[i], cudaEventDisableTiming);
        }
    }
};
static SideStream g_ss;

// ---------------- PTX helpers -------------------------------------------------
__device__ __forceinline__ uint32_t smem_to_u32(const void* p) {
    uint32_t a;
    asm("{ .reg .u64 t; cvta.to.shared.u64 t, %1; cvt.u32.u64 %0, t; }"
        : "=r"(a) : "l"(p));
    return a;
}
#define CP_ASYNC16(saddr, gaddr) \
    asm volatile("cp.async.cg.shared.global [%0], [%1], 16;" \
                 :: "r"(saddr), "l"(gaddr) : "memory")
#define CP_COMMIT() asm volatile("cp.async.commit_group;" ::: "memory")
#define CP_WAIT1()  asm volatile("cp.async.wait_group 1;" ::: "memory")
#define CP_WAIT0()  asm volatile("cp.async.wait_group 0;" ::: "memory")

#define LDSM4(r0, r1, r2, r3, addr) \
    asm volatile("ldmatrix.sync.aligned.m8n8.x4.shared.b16 {%0,%1,%2,%3}, [%4];" \
                 : "=r"(r0), "=r"(r1), "=r"(r2), "=r"(r3) : "r"(addr))

#define MMA_BF16(acc, a, b0v, b1v) \
    asm volatile("mma.sync.aligned.m16n8k16.row.col.f32.bf16.bf16.f32 " \
                 "{%0,%1,%2,%3}, {%4,%5,%6,%7}, {%8,%9}, {%0,%1,%2,%3};" \
                 : "+f"((acc)[0]), "+f"((acc)[1]), "+f"((acc)[2]), "+f"((acc)[3]) \
                 : "r"((a)[0]), "r"((a)[1]), "r"((a)[2]), "r"((a)[3]), \
                   "r"(b0v), "r"(b1v))

#define MMA_F16(acc, a, b0v, b1v) \
    asm volatile("mma.sync.aligned.m16n8k16.row.col.f32.f16.f16.f32 " \
                 "{%0,%1,%2,%3}, {%4,%5,%6,%7}, {%8,%9}, {%0,%1,%2,%3};" \
                 : "+f"((acc)[0]), "+f"((acc)[1]), "+f"((acc)[2]), "+f"((acc)[3]) \
                 : "r"((a)[0]), "r"((a)[1]), "r"((a)[2]), "r"((a)[3]), \
                   "r"(b0v), "r"(b1v))

// ---------------- tile geometry (swizzled, no padding) --------------------------
constexpr int MAT_B = 128 * 64;        // 8192 B
constexpr int BUF_B = 4 * MAT_B;       // Ah, Al, Bh, Bl -> 32 KB
constexpr int NSTAGE = 3;
constexpr int SMEM_GEMM = NSTAGE * BUF_B;   // 96 KB (fits occ 2)
constexpr int BUF_F = 2 * MAT_B;       // Af, Bf -> 16 KB
constexpr int SMEM_F16 = NSTAGE * BUF_F;    // 48 KB

__device__ __forceinline__ uint32_t sw_off(int row, int seg) {
    return (uint32_t)(row * 64 + ((seg ^ (row & 3)) << 4));
}

// ---------------------------------------------------------------------------
// split-bf16 GEMM (GEMM1 / GEMM2). 128x128 tile, 8 warps (4M x 2N), occ 2.
// MODE 0: fused target epilogue -> bf16 hi/lo.  MODE 1: fp32 out.
// ---------------------------------------------------------------------------
template <int MODE>
__global__ __launch_bounds__(256, 2) void k_gemm_mma(
    const __nv_bfloat16* __restrict__ Ah, const __nv_bfloat16* __restrict__ Al,
    size_t aStride,
    const __nv_bfloat16* __restrict__ Bh, const __nv_bfloat16* __restrict__ Bl,
    size_t bStride,
    const float* __restrict__ base, const float* __restrict__ bias,
    __nv_bfloat16* __restrict__ outH, __nv_bfloat16* __restrict__ outL,
    float* __restrict__ outF)
{
    extern __shared__ char smem[];
    const uint32_t sb = smem_to_u32(smem);
    const int tid = threadIdx.x, lane = tid & 31, wid = tid >> 5;
    const int warpM = wid & 3, warpN = wid >> 2;
    const int bz = blockIdx.z;
    const int mBase = blockIdx.y * 128, nBase = blockIdx.x * 128;

    const __nv_bfloat16* gmat[4] = {
        Ah + (size_t)bz * aStride + (size_t)mBase * 1024,
        Al + (size_t)bz * aStride + (size_t)mBase * 1024,
        Bh + (size_t)bz * bStride + (size_t)nBase * 1024,
        Bl + (size_t)bz * bStride + (size_t)nBase * 1024};

    auto issue = [&](int kc, int buf) {
        const uint32_t bufBase = sb + buf * BUF_B;
#pragma unroll
        for (int t = 0; t < 4; t++) {
            const __nv_bfloat16* g = gmat[t];
#pragma unroll
            for (int it = 0; it < 2; it++) {
                const int idx = it * 256 + tid;       // 0..511
                const int r = idx >> 2, s = idx & 3;
                CP_ASYNC16(bufBase + t * MAT_B + sw_off(r, s),
                           g + (size_t)r * 1024 + kc * 32 + s * 8);
            }
        }
        CP_COMMIT();
    };

    float acc[2][8][4];
#pragma unroll
    for (int mi = 0; mi < 2; mi++)
#pragma unroll
        for (int nt = 0; nt < 8; nt++)
#pragma unroll
            for (int j = 0; j < 4; j++) acc[mi][nt][j] = 0.0f;

    const uint32_t rr = (lane & 7) + ((lane >> 3) & 1) * 8;
    const int segHalf = lane >> 4;

    issue(0, 0);
    issue(1, 1);

    for (int kc = 0; kc < 32; kc++) {
        if (kc == 31) { CP_WAIT0(); } else { CP_WAIT1(); }
        __syncthreads();   // single barrier per chunk
        const uint32_t bufB = sb + (kc % NSTAGE) * BUF_B;
#pragma unroll
        for (int ks = 0; ks < 2; ks++) {
            const int seg = ks * 2 + segHalf;
            uint32_t a_h[2][4], a_l[2][4];
#pragma unroll
            for (int mi = 0; mi < 2; mi++) {
                const int row = warpM * 32 + mi * 16 + rr;
                const uint32_t ra = bufB + sw_off(row, seg);
                LDSM4(a_h[mi][0], a_h[mi][1], a_h[mi][2], a_h[mi][3], ra);
                LDSM4(a_l[mi][0], a_l[mi][1], a_l[mi][2], a_l[mi][3], ra + MAT_B);
            }
#pragma unroll
            for (int nj = 0; nj < 4; nj++) {
                const int row = warpN * 64 + nj * 16 + rr;
                const uint32_t rb = bufB + 2 * MAT_B + sw_off(row, seg);
                uint32_t b_h[4], b_l[4];
                LDSM4(b_h[0], b_h[1], b_h[2], b_h[3], rb);
                LDSM4(b_l[0], b_l[1], b_l[2], b_l[3], rb + MAT_B);
                MMA_BF16(acc[0][2 * nj],     a_h[0], b_h[0], b_h[2]);
                MMA_BF16(acc[0][2 * nj + 1], a_h[0], b_h[1], b_h[3]);
                MMA_BF16(acc[1][2 * nj],     a_h[1], b_h[0], b_h[2]);
                MMA_BF16(acc[1][2 * nj + 1], a_h[1], b_h[1], b_h[3]);
                MMA_BF16(acc[0][2 * nj],     a_h[0], b_l[0], b_l[2]);
                MMA_BF16(acc[0][2 * nj + 1], a_h[0], b_l[1], b_l[3]);
                MMA_BF16(acc[1][2 * nj],     a_h[1], b_l[0], b_l[2]);
                MMA_BF16(acc[1][2 * nj + 1], a_h[1], b_l[1], b_l[3]);
                MMA_BF16(acc[0][2 * nj],     a_l[0], b_h[0], b_h[2]);
                MMA_BF16(acc[0][2 * nj + 1], a_l[0], b_h[1], b_h[3]);
                MMA_BF16(acc[1][2 * nj],     a_l[1], b_h[0], b_h[2]);
                MMA_BF16(acc[1][2 * nj + 1], a_l[1], b_h[1], b_h[3]);
            }
        }
        if (kc + 2 < 32) issue(kc + 2, (kc + 2) % NSTAGE);
    }

    const int r0 = mBase + warpM * 32 + (lane >> 2);
    const int c0 = nBase + warpN * 64 + (lane & 3) * 2;

    if (MODE == 1) {
        float* ob = outF + (size_t)bz * MB1;
#pragma unroll
        for (int mi = 0; mi < 2; mi++)
#pragma unroll
            for (int nt = 0; nt < 8; nt++) {
                const int row = r0 + mi * 16;
                const int col = c0 + nt * 8;
                *reinterpret_cast<float2*>(ob + (size_t)row * 1024 + col) =
                    make_float2(acc[mi][nt][0], acc[mi][nt][1]);
                *reinterpret_cast<float2*>(ob + (size_t)(row + 8) * 1024 + col) =
                    make_float2(acc[mi][nt][2], acc[mi][nt][3]);
            }
    } else {
        const float* base_b = base + (size_t)bz * MB1;
        __nv_bfloat16* oh = outH + (size_t)bz * MB1;
        __nv_bfloat16* ol = outL + (size_t)bz * MB1;
#pragma unroll
        for (int mi = 0; mi < 2; mi++)
#pragma unroll
            for (int nt = 0; nt < 8; nt++) {
                const int col = c0 + nt * 8;
                const float bv0 = __ldg(bias + col);
                const float bv1 = __ldg(bias + col + 1);
#pragma unroll
                for (int hh = 0; hh < 2; hh++) {
                    const int row = r0 + mi * 16 + hh * 8;
                    float v0 = (acc[mi][nt][hh * 2 + 0] +
                                base_b[(size_t)col * 1024 + row] + bv0) * SCALE_W;
                    float v1 = (acc[mi][nt][hh * 2 + 1] +
                                base_b[(size_t)(col + 1) * 1024 + row] + bv1) * SCALE_W;
                    __nv_bfloat16 h0 = __float2bfloat16(v0);
                    __nv_bfloat16 h1 = __float2bfloat16(v1);
                    __nv_bfloat16 l0 = __float2bfloat16(v0 - __bfloat162float(h0));
                    __nv_bfloat16 l1 = __float2bfloat16(v1 - __bfloat162float(h1));
                    union { __nv_bfloat16 b[2]; uint32_t u; } ph, pl;
                    ph.b[0] = h0; ph.b[1] = h1;
                    pl.b[0] = l0; pl.b[1] = l1;
                    *reinterpret_cast<uint32_t*>(oh + (size_t)row * 1024 + col) = ph.u;
                    *reinterpret_cast<uint32_t*>(ol + (size_t)row * 1024 + col) = pl.u;
                }
            }
    }
}

// ---------------------------------------------------------------------------
// single-term fp16 GEMM (GEMM3): ctx[c,t] = sum_s comb[c,s] * attn[t,s]
// ---------------------------------------------------------------------------
__global__ __launch_bounds__(256, 2) void k_gemm_f16(
    const __half* __restrict__ A, const __half* __restrict__ B,
    float* __restrict__ outF)
{
    extern __shared__ char smem[];
    const uint32_t sb = smem_to_u32(smem);
    const int tid = threadIdx.x, lane = tid & 31, wid = tid >> 5;
    const int warpM = wid & 3, warpN = wid >> 2;
    const int bz = blockIdx.z;
    const int mBase = blockIdx.y * 128, nBase = blockIdx.x * 128;

    const __half* gmat[2] = {
        A + (size_t)bz * MB1 + (size_t)mBase * 1024,
        B + (size_t)bz * MB1 + (size_t)nBase * 1024};

    auto issue = [&](int kc, int buf) {
        const uint32_t bufBase = sb + buf * BUF_F;
#pragma unroll
        for (int t = 0; t < 2; t++) {
            const __half* g = gmat[t];
#pragma unroll
            for (int it = 0; it < 2; it++) {
                const int idx = it * 256 + tid;
                const int r = idx >> 2, s = idx & 3;
                CP_ASYNC16(bufBase + t * MAT_B + sw_off(r, s),
                           g + (size_t)r * 1024 + kc * 32 + s * 8);
            }
        }
        CP_COMMIT();
    };

    float acc[2][8][4];
#pragma unroll
    for (int mi = 0; mi < 2; mi++)
#pragma unroll
        for (int nt = 0; nt < 8; nt++)
#pragma unroll
            for (int j = 0; j < 4; j++) acc[mi][nt][j] = 0.0f;

    const uint32_t rr = (lane & 7) + ((lane >> 3) & 1) * 8;
    const int segHalf = lane >> 4;

    issue(0, 0);
    issue(1, 1);

    for (int kc = 0; kc < 32; kc++) {
        if (kc == 31) { CP_WAIT0(); } else { CP_WAIT1(); }
        __syncthreads();
        const uint32_t bufB = sb + (kc % NSTAGE) * BUF_F;
#pragma unroll
        for (int ks = 0; ks < 2; ks++) {
            const int seg = ks * 2 + segHalf;
            uint32_t a_f[2][4];
#pragma unroll
            for (int mi = 0; mi < 2; mi++) {
                const int row = warpM * 32 + mi * 16 + rr;
                LDSM4(a_f[mi][0], a_f[mi][1], a_f[mi][2], a_f[mi][3],
                      bufB + sw_off(row, seg));
            }
#pragma unroll
            for (int nj = 0; nj < 4; nj++) {
                const int row = warpN * 64 + nj * 16 + rr;
                uint32_t b_f[4];
                LDSM4(b_f[0], b_f[1], b_f[2], b_f[3],
                      bufB + MAT_B + sw_off(row, seg));
                MMA_F16(acc[0][2 * nj],     a_f[0], b_f[0], b_f[2]);
                MMA_F16(acc[0][2 * nj + 1], a_f[0], b_f[1], b_f[3]);
                MMA_F16(acc[1][2 * nj],     a_f[1], b_f[0], b_f[2]);
                MMA_F16(acc[1][2 * nj + 1], a_f[1], b_f[1], b_f[3]);
            }
        }
        if (kc + 2 < 32) issue(kc + 2, (kc + 2) % NSTAGE);
    }

    const int r0 = mBase + warpM * 32 + (lane >> 2);
    const int c0 = nBase + warpN * 64 + (lane & 3) * 2;
    float* ob = outF + (size_t)bz * MB1;
#pragma unroll
    for (int mi = 0; mi < 2; mi++)
#pragma unroll
        for (int nt = 0; nt < 8; nt++) {
            const int row = r0 + mi * 16;
            const int col = c0 + nt * 8;
            *reinterpret_cast<float2*>(ob + (size_t)row * 1024 + col) =
                make_float2(acc[mi][nt][0], acc[mi][nt][1]);
            *reinterpret_cast<float2*>(ob + (size_t)(row + 8) * 1024 + col) =
                make_float2(acc[mi][nt][2], acc[mi][nt][3]);
        }
}

// ---------------- elementwise split: f32 -> bf16 hi + lo (2x unrolled) ---------
__global__ __launch_bounds__(256) void k_split(const float* __restrict__ s,
                                               __nv_bfloat16* __restrict__ h,
                                               __nv_bfloat16* __restrict__ l,
                                               size_t n4) {
    size_t i = (size_t)blockIdx.x * blockDim.x + threadIdx.x;
    const size_t stride = (size_t)gridDim.x * blockDim.x;
    for (; i + stride < n4; i += 2 * stride) {
        float4 v0 = reinterpret_cast<const float4*>(s)[i];
        float4 v1 = reinterpret_cast<const float4*>(s)[i + stride];
        union { __nv_bfloat16 b[4]; uint2 u; } h0, l0, h1, l1;
        float f0[4] = {v0.x, v0.y, v0.z, v0.w};
        float f1[4] = {v1.x, v1.y, v1.z, v1.w};
#pragma unroll
        for (int j = 0; j < 4; j++) {
            __nv_bfloat16 hb0 = __float2bfloat16(f0[j]);
            __nv_bfloat16 hb1 = __float2bfloat16(f1[j]);
            h0.b[j] = hb0; l0.b[j] = __float2bfloat16(f0[j] - __bfloat162float(hb0));
            h1.b[j] = hb1; l1.b[j] = __float2bfloat16(f1[j] - __bfloat162float(hb1));
        }
        reinterpret_cast<uint2*>(h)[i] = h0.u;
        reinterpret_cast<uint2*>(l)[i] = l0.u;
        reinterpret_cast<uint2*>(h)[i + stride] = h1.u;
        reinterpret_cast<uint2*>(l)[i + stride] = l1.u;
    }
    for (; i < n4; i += stride) {
        float4 v = reinterpret_cast<const float4*>(s)[i];
        union { __nv_bfloat16 b[4]; uint2 u; } hh, ll;
        float f[4] = {v.x, v.y, v.z, v.w};
#pragma unroll
        for (int j = 0; j < 4; j++) {
            __nv_bfloat16 hb = __float2bfloat16(f[j]);
            hh.b[j] = hb;
            ll.b[j] = __float2bfloat16(f[j] - __bfloat162float(hb));
        }
        reinterpret_cast<uint2*>(h)[i] = hh.u;
        reinterpret_cast<uint2*>(l)[i] = ll.u;
    }
}

// ---------------- elementwise f32 -> fp16 (2x unrolled) -------------------------
__global__ __launch_bounds__(256) void k_half(const float* __restrict__ s,
                                              __half* __restrict__ d, size_t n4) {
    size_t i = (size_t)blockIdx.x * blockDim.x + threadIdx.x;
    const size_t stride = (size_t)gridDim.x * blockDim.x;
    for (; i + stride < n4; i += 2 * stride) {
        float4 v0 = reinterpret_cast<const float4*>(s)[i];
        float4 v1 = reinterpret_cast<const float4*>(s)[i + stride];
        union { __half h[4]; uint2 u; } a, b;
        a.h[0] = __float2half_rn(v0.x); a.h[1] = __float2half_rn(v0.y);
        a.h[2] = __float2half_rn(v0.z); a.h[3] = __float2half_rn(v0.w);
        b.h[0] = __float2half_rn(v1.x); b.h[1] = __float2half_rn(v1.y);
        b.h[2] = __float2half_rn(v1.z); b.h[3] = __float2half_rn(v1.w);
        reinterpret_cast<uint2*>(d)[i] = a.u;
        reinterpret_cast<uint2*>(d)[i + stride] = b.u;
    }
    for (; i < n4; i += stride) {
        float4 v = reinterpret_cast<const float4*>(s)[i];
        union { __half h[4]; uint2 u; } hf;
        hf.h[0] = __float2half_rn(v.x);
        hf.h[1] = __float2half_rn(v.y);
        hf.h[2] = __float2half_rn(v.z);
        hf.h[3] = __float2half_rn(v.w);
        reinterpret_cast<uint2*>(d)[i] = hf.u;
    }
}

// ---------------- transpose+split: [b][R][C] f32 -> [b][C][R] bf16 hi/lo -------
// 64(r) x 32(c) tile. Store phase: rp = lane -> each warp stores one full
// 64-row column as 32 consecutive bf16x2 (128B transaction).
__global__ __launch_bounds__(256) void k_tsplit(const float* __restrict__ src,
                                                __nv_bfloat16* __restrict__ h,
                                                __nv_bfloat16* __restrict__ l) {
    __shared__ float tile[32][65];     // [c][r], stride 65 avoids conflicts
    const int b = blockIdx.z;
    const int r0 = blockIdx.y * 64, c0 = blockIdx.x * 32;
    const int tid = threadIdx.x, lane = tid & 31, wid = tid >> 5;
    const float* sp = src + (size_t)b * MB1;

    // load: c = lane (coalesced 128B), r = wid + 8*i
#pragma unroll
    for (int i = 0; i < 8; i++) {
        const int r_l = wid + 8 * i;             // 0..63
        tile[lane][r_l] = sp[(size_t)(r0 + r_l) * 1024 + c0 + lane];
    }
    __syncthreads();

    // store: rp = lane (pairs 0..31 = rows 0..63 contiguous), c = wid + 8*i
    __nv_bfloat16* hb_ = h + (size_t)b * MB1;
    __nv_bfloat16* lb_ = l + (size_t)b * MB1;
#pragma unroll
    for (int i = 0; i < 4; i++) {
        const int c_w = wid + 8 * i;             // 0..31
        const float v0 = tile[c_w][2 * lane];
        const float v1 = tile[c_w][2 * lane + 1];
        __nv_bfloat16 h0 = __float2bfloat16(v0);
        __nv_bfloat16 h1 = __float2bfloat16(v1);
        __nv_bfloat16 l0 = __float2bfloat16(v0 - __bfloat162float(h0));
        __nv_bfloat16 l1 = __float2bfloat16(v1 - __bfloat162float(h1));
        union { __nv_bfloat16 b[2]; uint32_t u; } ph, pl;
        ph.b[0] = h0; ph.b[1] = h1;
        pl.b[0] = l0; pl.b[1] = l1;
        const size_t o = (size_t)(c0 + c_w) * 1024 + r0 + 2 * lane;
        *reinterpret_cast<uint32_t*>(hb_ + o) = ph.u;
        *reinterpret_cast<uint32_t*>(lb_ + o) = pl.u;
    }
}

// ---------------- softmax over S=1024, in place, fused fp16 write --------------
__global__ __launch_bounds__(256) void k_softmax_f16(float* __restrict__ attn,
                                                     __half* __restrict__ fh) {
    const size_t row = blockIdx.x;
    float* p = attn + row * 1024;
    const int tid = threadIdx.x;
    float4 v = reinterpret_cast<float4*>(p)[tid];
    __shared__ float red[8];
    float m = fmaxf(fmaxf(v.x, v.y), fmaxf(v.z, v.w));
#pragma unroll
    for (int o = 16; o > 0; o >>= 1) m = fmaxf(m, __shfl_xor_sync(~0u, m, o));
    if ((tid & 31) == 0) red[tid >> 5] = m;
    __syncthreads();
    float mm = red[0];
#pragma unroll
    for (int i = 1; i < 8; i++) mm = fmaxf(mm, red[i]);
    __syncthreads();
    v.x = expf(v.x - mm); v.y = expf(v.y - mm);
    v.z = expf(v.z - mm); v.w = expf(v.w - mm);
    float s = v.x + v.y + v.z + v.w;
#pragma unroll
    for (int o = 16; o > 0; o >>= 1) s += __shfl_xor_sync(~0u, s, o);
    if ((tid & 31) == 0) red[tid >> 5] = s;
    __syncthreads();
    float tot = 0.0f;
#pragma unroll
    for (int i = 0; i < 8; i++) tot += red[i];
    const float inv = 1.0f / tot;
    v.x *= inv; v.y *= inv; v.z *= inv; v.w *= inv;
    reinterpret_cast<float4*>(p)[tid] = v;

    union { __half h[4]; uint2 u; } hf;
    hf.h[0] = __float2half_rn(v.x);
    hf.h[1] = __float2half_rn(v.y);
    hf.h[2] = __float2half_rn(v.z);
    hf.h[3] = __float2half_rn(v.w);
    reinterpret_cast<uint2*>(fh + row * 1024)[tid] = hf.u;
}

// -------------------------------------------------------------------------------
extern "C" void kernel_launch(void* const* d_in, const int* in_sizes, int n_in,
                              void* d_out, int out_size) {
    const float* base = (const float*)d_in[0];  // [B,C,T,1]
    const float* x    = (const float*)d_in[1];  // [B,C,T,1]
    const float* top  = (const float*)d_in[2];  // [B,C,S]
    const float* comb = (const float*)d_in[3];  // [B,C,S]
    const float* W    = (const float*)d_in[4];  // [C,C]
    const float* bias = (const float*)d_in[5];  // [C]

    float* out  = (float*)d_out;
    float* ctx  = out;                     // [B,C,T]
    float* attn = out + (size_t)Bb * MB1;  // [B,T,S]

    void *pWh, *pWl, *pxh, *pxl, *pth, *ptl, *pgh, *pgl, *pcf, *paf;
    cudaGetSymbolAddress(&pWh, g_W_h);    cudaGetSymbolAddress(&pWl, g_W_l);
    cudaGetSymbolAddress(&pxh, g_xT_h);   cudaGetSymbolAddress(&pxl, g_xT_l);
    cudaGetSymbolAddress(&pth, g_topT_h); cudaGetSymbolAddress(&ptl, g_topT_l);
    cudaGetSymbolAddress(&pgh, g_tgt_h);  cudaGetSymbolAddress(&pgl, g_tgt_l);
    cudaGetSymbolAddress(&pcf, g_comb_f); cudaGetSymbolAddress(&paf, g_attn_f);

    cudaFuncSetAttribute(k_gemm_mma<0>, cudaFuncAttributeMaxDynamicSharedMemorySize, SMEM_GEMM);
    cudaFuncSetAttribute(k_gemm_mma<1>, cudaFuncAttributeMaxDynamicSharedMemorySize, SMEM_GEMM);
    cudaFuncSetAttribute(k_gemm_f16,    cudaFuncAttributeMaxDynamicSharedMemorySize, SMEM_F16);

    dim3 gGemm(8, 8, Bb), bGemm(256);
    dim3 gHalfG(8, 8, HB);               // half-batch GEMM grid (512 CTAs)
    dim3 gT(32, 16, Bb);                 // tsplit: 32 c-tiles x 16 r-tiles

    // ---- fork side stream: conversions not needed until GEMM2/GEMM3 ----------
    cudaEventRecord(g_ss.fork, 0);
    cudaStreamWaitEvent(g_ss.s2, g_ss.fork, 0);
    k_tsplit<<<gT, 256, 0, g_ss.s2>>>(top, (__nv_bfloat16*)pth, (__nv_bfloat16*)ptl);
    k_half<<<1184, 256, 0, g_ss.s2>>>(comb, (__half*)pcf, (size_t)Bb * MB1 / 4);
    cudaEventRecord(g_ss.join, g_ss.s2);

    // ---- main stream: GEMM1 prerequisites + GEMM1 ----------------------------
    k_split<<<512, 256>>>(W, (__nv_bfloat16*)pWh, (__nv_bfloat16*)pWl, MB1 / 4);
    k_tsplit<<<gT, 256>>>(x, (__nv_bfloat16*)pxh, (__nv_bfloat16*)pxl);

    // GEMM1: targetT[t,d] = (xT[t,c] . W[d,c] + base + bias) * scale (fused split)
    k_gemm_mma<0><<<gGemm, bGemm, SMEM_GEMM>>>(
        (const __nv_bfloat16*)pxh, (const __nv_bfloat16*)pxl, MB1,
        (const __nv_bfloat16*)pWh, (const __nv_bfloat16*)pWl, 0,
        base, bias, (__nv_bfloat16*)pgh, (__nv_bfloat16*)pgl, nullptr);

    // ---- join: topT (GEMM2) and comb_f (GEMM3) ready -------------------------
    cudaStreamWaitEvent(0, g_ss.join, 0);

    // ---- GEMM2 / softmax / GEMM3 in 2 half-batch segments ---------------------
    // stream0: G2(h0) -> G2(h1) -> G3(h0) -> G3(h1)
    // s2:      sm(h0) overlaps G2(h1); sm(h1) overlaps G3(h0)
    for (int h = 0; h < 2; h++) {
        const size_t off = (size_t)h * HB * MB1;
        k_gemm_mma<1><<<gHalfG, bGemm, SMEM_GEMM>>>(
            (const __nv_bfloat16*)pgh + off, (const __nv_bfloat16*)pgl + off, MB1,
            (const __nv_bfloat16*)pth + off, (const __nv_bfloat16*)ptl + off, MB1,
            nullptr, nullptr, nullptr, nullptr, attn + off);
        cudaEventRecord(g_ss.e_g2[h], 0);
        cudaStreamWaitEvent(g_ss.s2, g_ss.e_g2[h], 0);
        k_softmax_f16<<<HB * 1024, 256, 0, g_ss.s2>>>(attn + off, (__half*)paf + off);
        cudaEventRecord(g_ss.e_sm[h], g_ss.s2);
    }
    for (int h = 0; h < 2; h++) {
        const size_t off = (size_t)h * HB * MB1;
        cudaStreamWaitEvent(0, g_ss.e_sm[h], 0);
        k_gemm_f16<<<gHalfG, bGemm, SMEM_F16>>>(
            (const __half*)pcf + off, (const __half*)paf + off, ctx + off);
    }
}

// round 16
// speedup vs baseline: 1.0585x; 1.0585x over previous
#include <cuda_runtime.h>
#include <cuda_bf16.h>
#include <cuda_fp16.h>
#include <cstdint>

// ConvMultiStepAttention, B=16, C=T=S=1024.
//   targetT[b,t,d] = (base[b,d,t] + sum_c W[d,c] x[b,c,t] + bias[d]) * sqrt(0.5)
//   scores[b,t,s]  = sum_c targetT[b,t,c] * topT[b,s,c]
//   attn = softmax_S(scores)   (in d_out, in-place, fused fp16 write)
//   ctx[b,c,t]     = sum_s comb[b,c,s] * attn[b,t,s]
// GEMM1/2: split-bf16 (hh+hl+lh, fp32 acc). GEMM3: single fp16 pass.
// R16 (final): exact R14 configuration — the converged optimum.
//   - 128x128 GEMM tiles, XOR-swizzled smem, 3-stage cp.async, 1 barrier/chunk,
//     occ 2 (R8/R10)
//   - fp16 single-term GEMM3 + fused softmax->fp16 (R7)
//   - side-stream overlap of topT/comb conversions with GEMM1 (R11)
//   - warp-aligned 128B-store tsplit (R14)

#define SCALE_W 0.70710678118654752440f

constexpr int Bb = 16;
constexpr size_t MB1 = 1024 * 1024;

// ---------------- scratch ----------------------------------------------------
__device__ __nv_bfloat16 g_W_h[MB1],         g_W_l[MB1];
__device__ __nv_bfloat16 g_xT_h[Bb * MB1],   g_xT_l[Bb * MB1];
__device__ __nv_bfloat16 g_topT_h[Bb * MB1], g_topT_l[Bb * MB1];
__device__ __nv_bfloat16 g_tgt_h[Bb * MB1],  g_tgt_l[Bb * MB1];
__device__ __half        g_comb_f[Bb * MB1];
__device__ __half        g_attn_f[Bb * MB1];

// ---------------- host-side stream/event handles (created pre-checkpoint) ------
struct SideStream {
    cudaStream_t s2;
    cudaEvent_t  fork, join;
    SideStream() {
        cudaStreamCreateWithFlags(&s2, cudaStreamNonBlocking);
        cudaEventCreateWithFlags(&fork, cudaEventDisableTiming);
        cudaEventCreateWithFlags(&join, cudaEventDisableTiming);
    }
};
static SideStream g_ss;

// ---------------- PTX helpers -------------------------------------------------
__device__ __forceinline__ uint32_t smem_to_u32(const void* p) {
    uint32_t a;
    asm("{ .reg .u64 t; cvta.to.shared.u64 t, %1; cvt.u32.u64 %0, t; }"
        : "=r"(a) : "l"(p));
    return a;
}
#define CP_ASYNC16(saddr, gaddr) \
    asm volatile("cp.async.cg.shared.global [%0], [%1], 16;" \
                 :: "r"(saddr), "l"(gaddr) : "memory")
#define CP_COMMIT() asm volatile("cp.async.commit_group;" ::: "memory")
#define CP_WAIT1()  asm volatile("cp.async.wait_group 1;" ::: "memory")
#define CP_WAIT0()  asm volatile("cp.async.wait_group 0;" ::: "memory")

#define LDSM4(r0, r1, r2, r3, addr) \
    asm volatile("ldmatrix.sync.aligned.m8n8.x4.shared.b16 {%0,%1,%2,%3}, [%4];" \
                 : "=r"(r0), "=r"(r1), "=r"(r2), "=r"(r3) : "r"(addr))

#define MMA_BF16(acc, a, b0v, b1v) \
    asm volatile("mma.sync.aligned.m16n8k16.row.col.f32.bf16.bf16.f32 " \
                 "{%0,%1,%2,%3}, {%4,%5,%6,%7}, {%8,%9}, {%0,%1,%2,%3};" \
                 : "+f"((acc)[0]), "+f"((acc)[1]), "+f"((acc)[2]), "+f"((acc)[3]) \
                 : "r"((a)[0]), "r"((a)[1]), "r"((a)[2]), "r"((a)[3]), \
                   "r"(b0v), "r"(b1v))

#define MMA_F16(acc, a, b0v, b1v) \
    asm volatile("mma.sync.aligned.m16n8k16.row.col.f32.f16.f16.f32 " \
                 "{%0,%1,%2,%3}, {%4,%5,%6,%7}, {%8,%9}, {%0,%1,%2,%3};" \
                 : "+f"((acc)[0]), "+f"((acc)[1]), "+f"((acc)[2]), "+f"((acc)[3]) \
                 : "r"((a)[0]), "r"((a)[1]), "r"((a)[2]), "r"((a)[3]), \
                   "r"(b0v), "r"(b1v))

// ---------------- tile geometry (swizzled, no padding) --------------------------
constexpr int MAT_B = 128 * 64;        // 8192 B
constexpr int BUF_B = 4 * MAT_B;       // Ah, Al, Bh, Bl -> 32 KB
constexpr int NSTAGE = 3;
constexpr int SMEM_GEMM = NSTAGE * BUF_B;   // 96 KB (fits occ 2)
constexpr int BUF_F = 2 * MAT_B;       // Af, Bf -> 16 KB
constexpr int SMEM_F16 = NSTAGE * BUF_F;    // 48 KB

__device__ __forceinline__ uint32_t sw_off(int row, int seg) {
    return (uint32_t)(row * 64 + ((seg ^ (row & 3)) << 4));
}

// ---------------------------------------------------------------------------
// split-bf16 GEMM (GEMM1 / GEMM2). 128x128 tile, 8 warps (4M x 2N), occ 2.
// MODE 0: fused target epilogue -> bf16 hi/lo.  MODE 1: fp32 out.
// ---------------------------------------------------------------------------
template <int MODE>
__global__ __launch_bounds__(256, 2) void k_gemm_mma(
    const __nv_bfloat16* __restrict__ Ah, const __nv_bfloat16* __restrict__ Al,
    size_t aStride,
    const __nv_bfloat16* __restrict__ Bh, const __nv_bfloat16* __restrict__ Bl,
    size_t bStride,
    const float* __restrict__ base, const float* __restrict__ bias,
    __nv_bfloat16* __restrict__ outH, __nv_bfloat16* __restrict__ outL,
    float* __restrict__ outF)
{
    extern __shared__ char smem[];
    const uint32_t sb = smem_to_u32(smem);
    const int tid = threadIdx.x, lane = tid & 31, wid = tid >> 5;
    const int warpM = wid & 3, warpN = wid >> 2;
    const int bz = blockIdx.z;
    const int mBase = blockIdx.y * 128, nBase = blockIdx.x * 128;

    const __nv_bfloat16* gmat[4] = {
        Ah + (size_t)bz * aStride + (size_t)mBase * 1024,
        Al + (size_t)bz * aStride + (size_t)mBase * 1024,
        Bh + (size_t)bz * bStride + (size_t)nBase * 1024,
        Bl + (size_t)bz * bStride + (size_t)nBase * 1024};

    auto issue = [&](int kc, int buf) {
        const uint32_t bufBase = sb + buf * BUF_B;
#pragma unroll
        for (int t = 0; t < 4; t++) {
            const __nv_bfloat16* g = gmat[t];
#pragma unroll
            for (int it = 0; it < 2; it++) {
                const int idx = it * 256 + tid;       // 0..511
                const int r = idx >> 2, s = idx & 3;
                CP_ASYNC16(bufBase + t * MAT_B + sw_off(r, s),
                           g + (size_t)r * 1024 + kc * 32 + s * 8);
            }
        }
        CP_COMMIT();
    };

    float acc[2][8][4];
#pragma unroll
    for (int mi = 0; mi < 2; mi++)
#pragma unroll
        for (int nt = 0; nt < 8; nt++)
#pragma unroll
            for (int j = 0; j < 4; j++) acc[mi][nt][j] = 0.0f;

    const uint32_t rr = (lane & 7) + ((lane >> 3) & 1) * 8;
    const int segHalf = lane >> 4;

    issue(0, 0);
    issue(1, 1);

    for (int kc = 0; kc < 32; kc++) {
        if (kc == 31) { CP_WAIT0(); } else { CP_WAIT1(); }
        __syncthreads();   // single barrier per chunk
        const uint32_t bufB = sb + (kc % NSTAGE) * BUF_B;
#pragma unroll
        for (int ks = 0; ks < 2; ks++) {
            const int seg = ks * 2 + segHalf;
            uint32_t a_h[2][4], a_l[2][4];
#pragma unroll
            for (int mi = 0; mi < 2; mi++) {
                const int row = warpM * 32 + mi * 16 + rr;
                const uint32_t ra = bufB + sw_off(row, seg);
                LDSM4(a_h[mi][0], a_h[mi][1], a_h[mi][2], a_h[mi][3], ra);
                LDSM4(a_l[mi][0], a_l[mi][1], a_l[mi][2], a_l[mi][3], ra + MAT_B);
            }
#pragma unroll
            for (int nj = 0; nj < 4; nj++) {
                const int row = warpN * 64 + nj * 16 + rr;
                const uint32_t rb = bufB + 2 * MAT_B + sw_off(row, seg);
                uint32_t b_h[4], b_l[4];
                LDSM4(b_h[0], b_h[1], b_h[2], b_h[3], rb);
                LDSM4(b_l[0], b_l[1], b_l[2], b_l[3], rb + MAT_B);
                MMA_BF16(acc[0][2 * nj],     a_h[0], b_h[0], b_h[2]);
                MMA_BF16(acc[0][2 * nj + 1], a_h[0], b_h[1], b_h[3]);
                MMA_BF16(acc[1][2 * nj],     a_h[1], b_h[0], b_h[2]);
                MMA_BF16(acc[1][2 * nj + 1], a_h[1], b_h[1], b_h[3]);
                MMA_BF16(acc[0][2 * nj],     a_h[0], b_l[0], b_l[2]);
                MMA_BF16(acc[0][2 * nj + 1], a_h[0], b_l[1], b_l[3]);
                MMA_BF16(acc[1][2 * nj],     a_h[1], b_l[0], b_l[2]);
                MMA_BF16(acc[1][2 * nj + 1], a_h[1], b_l[1], b_l[3]);
                MMA_BF16(acc[0][2 * nj],     a_l[0], b_h[0], b_h[2]);
                MMA_BF16(acc[0][2 * nj + 1], a_l[0], b_h[1], b_h[3]);
                MMA_BF16(acc[1][2 * nj],     a_l[1], b_h[0], b_h[2]);
                MMA_BF16(acc[1][2 * nj + 1], a_l[1], b_h[1], b_h[3]);
            }
        }
        if (kc + 2 < 32) issue(kc + 2, (kc + 2) % NSTAGE);
    }

    const int r0 = mBase + warpM * 32 + (lane >> 2);
    const int c0 = nBase + warpN * 64 + (lane & 3) * 2;

    if (MODE == 1) {
        float* ob = outF + (size_t)bz * MB1;
#pragma unroll
        for (int mi = 0; mi < 2; mi++)
#pragma unroll
            for (int nt = 0; nt < 8; nt++) {
                const int row = r0 + mi * 16;
                const int col = c0 + nt * 8;
                *reinterpret_cast<float2*>(ob + (size_t)row * 1024 + col) =
                    make_float2(acc[mi][nt][0], acc[mi][nt][1]);
                *reinterpret_cast<float2*>(ob + (size_t)(row + 8) * 1024 + col) =
                    make_float2(acc[mi][nt][2], acc[mi][nt][3]);
            }
    } else {
        const float* base_b = base + (size_t)bz * MB1;
        __nv_bfloat16* oh = outH + (size_t)bz * MB1;
        __nv_bfloat16* ol = outL + (size_t)bz * MB1;
#pragma unroll
        for (int mi = 0; mi < 2; mi++)
#pragma unroll
            for (int nt = 0; nt < 8; nt++) {
                const int col = c0 + nt * 8;
                const float bv0 = __ldg(bias + col);
                const float bv1 = __ldg(bias + col + 1);
#pragma unroll
                for (int hh = 0; hh < 2; hh++) {
                    const int row = r0 + mi * 16 + hh * 8;
                    float v0 = (acc[mi][nt][hh * 2 + 0] +
                                base_b[(size_t)col * 1024 + row] + bv0) * SCALE_W;
                    float v1 = (acc[mi][nt][hh * 2 + 1] +
                                base_b[(size_t)(col + 1) * 1024 + row] + bv1) * SCALE_W;
                    __nv_bfloat16 h0 = __float2bfloat16(v0);
                    __nv_bfloat16 h1 = __float2bfloat16(v1);
                    __nv_bfloat16 l0 = __float2bfloat16(v0 - __bfloat162float(h0));
                    __nv_bfloat16 l1 = __float2bfloat16(v1 - __bfloat162float(h1));
                    union { __nv_bfloat16 b[2]; uint32_t u; } ph, pl;
                    ph.b[0] = h0; ph.b[1] = h1;
                    pl.b[0] = l0; pl.b[1] = l1;
                    *reinterpret_cast<uint32_t*>(oh + (size_t)row * 1024 + col) = ph.u;
                    *reinterpret_cast<uint32_t*>(ol + (size_t)row * 1024 + col) = pl.u;
                }
            }
    }
}

// ---------------------------------------------------------------------------
// single-term fp16 GEMM (GEMM3): ctx[c,t] = sum_s comb[c,s] * attn[t,s]
// ---------------------------------------------------------------------------
__global__ __launch_bounds__(256, 2) void k_gemm_f16(
    const __half* __restrict__ A, const __half* __restrict__ B,
    float* __restrict__ outF)
{
    extern __shared__ char smem[];
    const uint32_t sb = smem_to_u32(smem);
    const int tid = threadIdx.x, lane = tid & 31, wid = tid >> 5;
    const int warpM = wid & 3, warpN = wid >> 2;
    const int bz = blockIdx.z;
    const int mBase = blockIdx.y * 128, nBase = blockIdx.x * 128;

    const __half* gmat[2] = {
        A + (size_t)bz * MB1 + (size_t)mBase * 1024,
        B + (size_t)bz * MB1 + (size_t)nBase * 1024};

    auto issue = [&](int kc, int buf) {
        const uint32_t bufBase = sb + buf * BUF_F;
#pragma unroll
        for (int t = 0; t < 2; t++) {
            const __half* g = gmat[t];
#pragma unroll
            for (int it = 0; it < 2; it++) {
                const int idx = it * 256 + tid;
                const int r = idx >> 2, s = idx & 3;
                CP_ASYNC16(bufBase + t * MAT_B + sw_off(r, s),
                           g + (size_t)r * 1024 + kc * 32 + s * 8);
            }
        }
        CP_COMMIT();
    };

    float acc[2][8][4];
#pragma unroll
    for (int mi = 0; mi < 2; mi++)
#pragma unroll
        for (int nt = 0; nt < 8; nt++)
#pragma unroll
            for (int j = 0; j < 4; j++) acc[mi][nt][j] = 0.0f;

    const uint32_t rr = (lane & 7) + ((lane >> 3) & 1) * 8;
    const int segHalf = lane >> 4;

    issue(0, 0);
    issue(1, 1);

    for (int kc = 0; kc < 32; kc++) {
        if (kc == 31) { CP_WAIT0(); } else { CP_WAIT1(); }
        __syncthreads();
        const uint32_t bufB = sb + (kc % NSTAGE) * BUF_F;
#pragma unroll
        for (int ks = 0; ks < 2; ks++) {
            const int seg = ks * 2 + segHalf;
            uint32_t a_f[2][4];
#pragma unroll
            for (int mi = 0; mi < 2; mi++) {
                const int row = warpM * 32 + mi * 16 + rr;
                LDSM4(a_f[mi][0], a_f[mi][1], a_f[mi][2], a_f[mi][3],
                      bufB + sw_off(row, seg));
            }
#pragma unroll
            for (int nj = 0; nj < 4; nj++) {
                const int row = warpN * 64 + nj * 16 + rr;
                uint32_t b_f[4];
                LDSM4(b_f[0], b_f[1], b_f[2], b_f[3],
                      bufB + MAT_B + sw_off(row, seg));
                MMA_F16(acc[0][2 * nj],     a_f[0], b_f[0], b_f[2]);
                MMA_F16(acc[0][2 * nj + 1], a_f[0], b_f[1], b_f[3]);
                MMA_F16(acc[1][2 * nj],     a_f[1], b_f[0], b_f[2]);
                MMA_F16(acc[1][2 * nj + 1], a_f[1], b_f[1], b_f[3]);
            }
        }
        if (kc + 2 < 32) issue(kc + 2, (kc + 2) % NSTAGE);
    }

    const int r0 = mBase + warpM * 32 + (lane >> 2);
    const int c0 = nBase + warpN * 64 + (lane & 3) * 2;
    float* ob = outF + (size_t)bz * MB1;
#pragma unroll
    for (int mi = 0; mi < 2; mi++)
#pragma unroll
        for (int nt = 0; nt < 8; nt++) {
            const int row = r0 + mi * 16;
            const int col = c0 + nt * 8;
            *reinterpret_cast<float2*>(ob + (size_t)row * 1024 + col) =
                make_float2(acc[mi][nt][0], acc[mi][nt][1]);
            *reinterpret_cast<float2*>(ob + (size_t)(row + 8) * 1024 + col) =
                make_float2(acc[mi][nt][2], acc[mi][nt][3]);
        }
}

// ---------------- elementwise split: f32 -> bf16 hi + lo (2x unrolled) ---------
__global__ __launch_bounds__(256) void k_split(const float* __restrict__ s,
                                               __nv_bfloat16* __restrict__ h,
                                               __nv_bfloat16* __restrict__ l,
                                               size_t n4) {
    size_t i = (size_t)blockIdx.x * blockDim.x + threadIdx.x;
    const size_t stride = (size_t)gridDim.x * blockDim.x;
    for (; i + stride < n4; i += 2 * stride) {
        float4 v0 = reinterpret_cast<const float4*>(s)[i];
        float4 v1 = reinterpret_cast<const float4*>(s)[i + stride];
        union { __nv_bfloat16 b[4]; uint2 u; } h0, l0, h1, l1;
        float f0[4] = {v0.x, v0.y, v0.z, v0.w};
        float f1[4] = {v1.x, v1.y, v1.z, v1.w};
#pragma unroll
        for (int j = 0; j < 4; j++) {
            __nv_bfloat16 hb0 = __float2bfloat16(f0[j]);
            __nv_bfloat16 hb1 = __float2bfloat16(f1[j]);
            h0.b[j] = hb0; l0.b[j] = __float2bfloat16(f0[j] - __bfloat162float(hb0));
            h1.b[j] = hb1; l1.b[j] = __float2bfloat16(f1[j] - __bfloat162float(hb1));
        }
        reinterpret_cast<uint2*>(h)[i] = h0.u;
        reinterpret_cast<uint2*>(l)[i] = l0.u;
        reinterpret_cast<uint2*>(h)[i + stride] = h1.u;
        reinterpret_cast<uint2*>(l)[i + stride] = l1.u;
    }
    for (; i < n4; i += stride) {
        float4 v = reinterpret_cast<const float4*>(s)[i];
        union { __nv_bfloat16 b[4]; uint2 u; } hh, ll;
        float f[4] = {v.x, v.y, v.z, v.w};
#pragma unroll
        for (int j = 0; j < 4; j++) {
            __nv_bfloat16 hb = __float2bfloat16(f[j]);
            hh.b[j] = hb;
            ll.b[j] = __float2bfloat16(f[j] - __bfloat162float(hb));
        }
        reinterpret_cast<uint2*>(h)[i] = hh.u;
        reinterpret_cast<uint2*>(l)[i] = ll.u;
    }
}

// ---------------- elementwise f32 -> fp16 (2x unrolled) -------------------------
__global__ __launch_bounds__(256) void k_half(const float* __restrict__ s,
                                              __half* __restrict__ d, size_t n4) {
    size_t i = (size_t)blockIdx.x * blockDim.x + threadIdx.x;
    const size_t stride = (size_t)gridDim.x * blockDim.x;
    for (; i + stride < n4; i += 2 * stride) {
        float4 v0 = reinterpret_cast<const float4*>(s)[i];
        float4 v1 = reinterpret_cast<const float4*>(s)[i + stride];
        union { __half h[4]; uint2 u; } a, b;
        a.h[0] = __float2half_rn(v0.x); a.h[1] = __float2half_rn(v0.y);
        a.h[2] = __float2half_rn(v0.z); a.h[3] = __float2half_rn(v0.w);
        b.h[0] = __float2half_rn(v1.x); b.h[1] = __float2half_rn(v1.y);
        b.h[2] = __float2half_rn(v1.z); b.h[3] = __float2half_rn(v1.w);
        reinterpret_cast<uint2*>(d)[i] = a.u;
        reinterpret_cast<uint2*>(d)[i + stride] = b.u;
    }
    for (; i < n4; i += stride) {
        float4 v = reinterpret_cast<const float4*>(s)[i];
        union { __half h[4]; uint2 u; } hf;
        hf.h[0] = __float2half_rn(v.x);
        hf.h[1] = __float2half_rn(v.y);
        hf.h[2] = __float2half_rn(v.z);
        hf.h[3] = __float2half_rn(v.w);
        reinterpret_cast<uint2*>(d)[i] = hf.u;
    }
}

// ---------------- transpose+split: [b][R][C] f32 -> [b][C][R] bf16 hi/lo -------
// 64(r) x 32(c) tile. Store phase: rp = lane -> each warp stores one full
// 64-row column as 32 consecutive bf16x2 (128B transaction).
__global__ __launch_bounds__(256) void k_tsplit(const float* __restrict__ src,
                                                __nv_bfloat16* __restrict__ h,
                                                __nv_bfloat16* __restrict__ l) {
    __shared__ float tile[32][65];     // [c][r], stride 65 avoids conflicts
    const int b = blockIdx.z;
    const int r0 = blockIdx.y * 64, c0 = blockIdx.x * 32;
    const int tid = threadIdx.x, lane = tid & 31, wid = tid >> 5;
    const float* sp = src + (size_t)b * MB1;

    // load: c = lane (coalesced 128B), r = wid + 8*i
#pragma unroll
    for (int i = 0; i < 8; i++) {
        const int r_l = wid + 8 * i;             // 0..63
        tile[lane][r_l] = sp[(size_t)(r0 + r_l) * 1024 + c0 + lane];
    }
    __syncthreads();

    // store: rp = lane (pairs 0..31 = rows 0..63 contiguous), c = wid + 8*i
    __nv_bfloat16* hb_ = h + (size_t)b * MB1;
    __nv_bfloat16* lb_ = l + (size_t)b * MB1;
#pragma unroll
    for (int i = 0; i < 4; i++) {
        const int c_w = wid + 8 * i;             // 0..31
        const float v0 = tile[c_w][2 * lane];
        const float v1 = tile[c_w][2 * lane + 1];
        __nv_bfloat16 h0 = __float2bfloat16(v0);
        __nv_bfloat16 h1 = __float2bfloat16(v1);
        __nv_bfloat16 l0 = __float2bfloat16(v0 - __bfloat162float(h0));
        __nv_bfloat16 l1 = __float2bfloat16(v1 - __bfloat162float(h1));
        union { __nv_bfloat16 b[2]; uint32_t u; } ph, pl;
        ph.b[0] = h0; ph.b[1] = h1;
        pl.b[0] = l0; pl.b[1] = l1;
        const size_t o = (size_t)(c0 + c_w) * 1024 + r0 + 2 * lane;
        *reinterpret_cast<uint32_t*>(hb_ + o) = ph.u;
        *reinterpret_cast<uint32_t*>(lb_ + o) = pl.u;
    }
}

// ---------------- softmax over S=1024, in place, fused fp16 write --------------
__global__ __launch_bounds__(256) void k_softmax_f16(float* __restrict__ attn,
                                                     __half* __restrict__ fh) {
    const size_t row = blockIdx.x;
    float* p = attn + row * 1024;
    const int tid = threadIdx.x;
    float4 v = reinterpret_cast<float4*>(p)[tid];
    __shared__ float red[8];
    float m = fmaxf(fmaxf(v.x, v.y), fmaxf(v.z, v.w));
#pragma unroll
    for (int o = 16; o > 0; o >>= 1) m = fmaxf(m, __shfl_xor_sync(~0u, m, o));
    if ((tid & 31) == 0) red[tid >> 5] = m;
    __syncthreads();
    float mm = red[0];
#pragma unroll
    for (int i = 1; i < 8; i++) mm = fmaxf(mm, red[i]);
    __syncthreads();
    v.x = expf(v.x - mm); v.y = expf(v.y - mm);
    v.z = expf(v.z - mm); v.w = expf(v.w - mm);
    float s = v.x + v.y + v.z + v.w;
#pragma unroll
    for (int o = 16; o > 0; o >>= 1) s += __shfl_xor_sync(~0u, s, o);
    if ((tid & 31) == 0) red[tid >> 5] = s;
    __syncthreads();
    float tot = 0.0f;
#pragma unroll
    for (int i = 0; i < 8; i++) tot += red[i];
    const float inv = 1.0f / tot;
    v.x *= inv; v.y *= inv; v.z *= inv; v.w *= inv;
    reinterpret_cast<float4*>(p)[tid] = v;

    union { __half h[4]; uint2 u; } hf;
    hf.h[0] = __float2half_rn(v.x);
    hf.h[1] = __float2half_rn(v.y);
    hf.h[2] = __float2half_rn(v.z);
    hf.h[3] = __float2half_rn(v.w);
    reinterpret_cast<uint2*>(fh + row * 1024)[tid] = hf.u;
}

// -------------------------------------------------------------------------------
extern "C" void kernel_launch(void* const* d_in, const int* in_sizes, int n_in,
                              void* d_out, int out_size) {
    const float* base = (const float*)d_in[0];  // [B,C,T,1]
    const float* x    = (const float*)d_in[1];  // [B,C,T,1]
    const float* top  = (const float*)d_in[2];  // [B,C,S]
    const float* comb = (const float*)d_in[3];  // [B,C,S]
    const float* W    = (const float*)d_in[4];  // [C,C]
    const float* bias = (const float*)d_in[5];  // [C]

    float* out  = (float*)d_out;
    float* ctx  = out;                     // [B,C,T]
    float* attn = out + (size_t)Bb * MB1;  // [B,T,S]

    void *pWh, *pWl, *pxh, *pxl, *pth, *ptl, *pgh, *pgl, *pcf, *paf;
    cudaGetSymbolAddress(&pWh, g_W_h);    cudaGetSymbolAddress(&pWl, g_W_l);
    cudaGetSymbolAddress(&pxh, g_xT_h);   cudaGetSymbolAddress(&pxl, g_xT_l);
    cudaGetSymbolAddress(&pth, g_topT_h); cudaGetSymbolAddress(&ptl, g_topT_l);
    cudaGetSymbolAddress(&pgh, g_tgt_h);  cudaGetSymbolAddress(&pgl, g_tgt_l);
    cudaGetSymbolAddress(&pcf, g_comb_f); cudaGetSymbolAddress(&paf, g_attn_f);

    cudaFuncSetAttribute(k_gemm_mma<0>, cudaFuncAttributeMaxDynamicSharedMemorySize, SMEM_GEMM);
    cudaFuncSetAttribute(k_gemm_mma<1>, cudaFuncAttributeMaxDynamicSharedMemorySize, SMEM_GEMM);
    cudaFuncSetAttribute(k_gemm_f16,    cudaFuncAttributeMaxDynamicSharedMemorySize, SMEM_F16);

    dim3 gGemm(8, 8, Bb), bGemm(256);
    dim3 gT(32, 16, Bb);                 // tsplit: 32 c-tiles x 16 r-tiles (64 rows)

    // ---- fork side stream: conversions not needed until GEMM2/GEMM3 ----------
    cudaEventRecord(g_ss.fork, 0);
    cudaStreamWaitEvent(g_ss.s2, g_ss.fork, 0);
    k_tsplit<<<gT, 256, 0, g_ss.s2>>>(top, (__nv_bfloat16*)pth, (__nv_bfloat16*)ptl);
    k_half<<<1184, 256, 0, g_ss.s2>>>(comb, (__half*)pcf, (size_t)Bb * MB1 / 4);
    cudaEventRecord(g_ss.join, g_ss.s2);

    // ---- main stream: GEMM1 prerequisites + GEMM1 ----------------------------
    k_split<<<512, 256>>>(W, (__nv_bfloat16*)pWh, (__nv_bfloat16*)pWl, MB1 / 4);
    k_tsplit<<<gT, 256>>>(x, (__nv_bfloat16*)pxh, (__nv_bfloat16*)pxl);

    // GEMM1: targetT[t,d] = (xT[t,c] . W[d,c] + base + bias) * scale (fused split)
    k_gemm_mma<0><<<gGemm, bGemm, SMEM_GEMM>>>(
        (const __nv_bfloat16*)pxh, (const __nv_bfloat16*)pxl, MB1,
        (const __nv_bfloat16*)pWh, (const __nv_bfloat16*)pWl, 0,
        base, bias, (__nv_bfloat16*)pgh, (__nv_bfloat16*)pgl, nullptr);

    // ---- join: topT (GEMM2) and comb_f (GEMM3) ready -------------------------
    cudaStreamWaitEvent(0, g_ss.join, 0);

    // GEMM2: scores[t,s] = targetT[t,c] . topT[s,c]
    k_gemm_mma<1><<<gGemm, bGemm, SMEM_GEMM>>>(
        (const __nv_bfloat16*)pgh, (const __nv_bfloat16*)pgl, MB1,
        (const __nv_bfloat16*)pth, (const __nv_bfloat16*)ptl, MB1,
        nullptr, nullptr, nullptr, nullptr, attn);

    // softmax + fused fp16 attn write
    k_softmax_f16<<<Bb * 1024, 256>>>(attn, (__half*)paf);

    // GEMM3 (fp16 single term): ctx[c,t] = comb[c,s] . attn[t,s]
    k_gemm_f16<<<gGemm, bGemm, SMEM_F16>>>(
        (const __half*)pcf, (const __half*)paf, ctx);
}